// round 10
// baseline (speedup 1.0000x reference)
#include <cuda_runtime.h>
#include <cuda_bf16.h>
#include <cstdint>

// Problem constants
#define NCHUNK  256            // BATCH * NPEAK
#define CHLEN   512
#define HID     256
#define MDIM    283
#define KPADP   320            // proj K padded to 10*32
#define DEPTH   7
#define HLC     131072         // CHLEN * HID elements per chunk, [l][c] layout
#define NROWS   131072         // total l rows (NCHUNK * CHLEN)
#define BUF_ELEMS ((size_t)NCHUNK * HLC)

// Activation ping-pong buffers, split bf16 (hi + lo reconstructs fp32 to ~2^-18)
__device__ __nv_bfloat16 g_hiA[BUF_ELEMS];
__device__ __nv_bfloat16 g_loA[BUF_ELEMS];
__device__ __nv_bfloat16 g_hiB[BUF_ELEMS];
__device__ __nv_bfloat16 g_loB[BUF_ELEMS];

// Pre-split tower weights: [layer][tap][o][i], bf16 hi/lo
#define WPLANE 65536                               // 256*256 per (layer,tap)
__device__ __nv_bfloat16 g_wHi[DEPTH * 3 * WPLANE];
__device__ __nv_bfloat16 g_wLo[DEPTH * 3 * WPLANE];

// Pre-split x and w_proj, K padded to 320
__device__ __nv_bfloat16 g_xHi[(size_t)NROWS * KPADP];
__device__ __nv_bfloat16 g_xLo[(size_t)NROWS * KPADP];
__device__ __nv_bfloat16 g_wpHi[HID * KPADP];
__device__ __nv_bfloat16 g_wpLo[HID * KPADP];

__device__ __forceinline__ uint32_t smem_u32(const void* p) {
    uint32_t a;
    asm("{ .reg .u64 t; cvta.to.shared.u64 t, %1; cvt.u32.u64 %0, t; }" : "=r"(a) : "l"(p));
    return a;
}
__device__ __forceinline__ void split_bf16(float v, __nv_bfloat16& h, __nv_bfloat16& l) {
    h = __float2bfloat16(v);
    l = __float2bfloat16(v - __bfloat162float(h));
}
__device__ __forceinline__ void ldsm_x4(uint32_t* r, uint32_t addr) {
    asm volatile("ldmatrix.sync.aligned.m8n8.x4.shared.b16 {%0,%1,%2,%3}, [%4];"
        : "=r"(r[0]), "=r"(r[1]), "=r"(r[2]), "=r"(r[3]) : "r"(addr));
}
__device__ __forceinline__ void mma_16816(float* d, const uint32_t* a, const uint32_t* b) {
    asm volatile("mma.sync.aligned.m16n8k16.row.col.f32.bf16.bf16.f32 "
        "{%0,%1,%2,%3},{%4,%5,%6,%7},{%8,%9},{%0,%1,%2,%3};"
        : "+f"(d[0]), "+f"(d[1]), "+f"(d[2]), "+f"(d[3])
        : "r"(a[0]), "r"(a[1]), "r"(a[2]), "r"(a[3]), "r"(b[0]), "r"(b[1]));
}
__device__ __forceinline__ void cp16(uint32_t dst, const void* src, int srcsize) {
    asm volatile("cp.async.cg.shared.global [%0], [%1], 16, %2;"
                 :: "r"(dst), "l"(src), "r"(srcsize) : "memory");
}
__device__ __forceinline__ void cp_commit() {
    asm volatile("cp.async.commit_group;" ::: "memory");
}
__device__ __forceinline__ void cp_wait1() {
    asm volatile("cp.async.wait_group 1;" ::: "memory");
}
__device__ __forceinline__ void cp_wait0() {
    asm volatile("cp.async.wait_group 0;" ::: "memory");
}

// ---------------------------------------------------------------------------
// Prep kernels
// ---------------------------------------------------------------------------
__global__ __launch_bounds__(256) void wprep_kernel(
    const float* __restrict__ w, __nv_bfloat16* __restrict__ whi,
    __nv_bfloat16* __restrict__ wlo)
{
    size_t j = (size_t)blockIdx.x * 256 + threadIdx.x;     // < DEPTH*3*WPLANE
    int layer = (int)(j / (3 * WPLANE));
    int rem   = (int)(j % (3 * WPLANE));
    int t  = rem / WPLANE;
    int oi = rem % WPLANE;                                  // o*256 + i
    float v = w[(size_t)layer * 3 * WPLANE + (size_t)oi * 3 + t];
    __nv_bfloat16 h, l;
    split_bf16(v, h, l);
    whi[j] = h;
    wlo[j] = l;
}

__global__ __launch_bounds__(256) void xsplit_kernel(
    const float* __restrict__ x, __nv_bfloat16* __restrict__ xh,
    __nv_bfloat16* __restrict__ xl)
{
    const size_t row = blockIdx.x;                          // < NROWS
    for (int m = threadIdx.x; m < KPADP; m += 256) {
        float v = (m < MDIM) ? x[row * MDIM + m] : 0.f;
        __nv_bfloat16 h, l;
        split_bf16(v, h, l);
        xh[row * KPADP + m] = h;
        xl[row * KPADP + m] = l;
    }
}

__global__ __launch_bounds__(256) void wpsplit_kernel(
    const float* __restrict__ wp, __nv_bfloat16* __restrict__ wh,
    __nv_bfloat16* __restrict__ wl)
{
    const size_t c = blockIdx.x;                            // < HID
    for (int m = threadIdx.x; m < KPADP; m += 256) {
        float v = (m < MDIM) ? wp[c * MDIM + m] : 0.f;
        __nv_bfloat16 h, l;
        split_bf16(v, h, l);
        wh[c * KPADP + m] = h;
        wl[c * KPADP + m] = l;
    }
}

// ---------------------------------------------------------------------------
// Wide-tile pipelined mma geometry.
// CTA: 128 M x 256 N; 8 warps (2x4), warp tile 64x64; phase K=32.
// Stage: A(128x32) hi/lo + B(256x32) hi/lo, LDA=40 (80B stride).
//   ABUF=10240, BBUF=20480, stage=61440, 2 stages = 122880 B. 1 CTA/SM.
// Fill: 4 threads/row x 16B; A = 2 row-halves, B = 4 row-quarters.
// Epilogue: processed in two 128-l halves, smem reused as [128][136] bf16 x2.
// ---------------------------------------------------------------------------
#define LDA     40
#define ABUF    10240
#define BBUF    20480
#define STG_SZ  61440
#define SM_PIPE 122880

// ---------------------------------------------------------------------------
// Projection via mma: D[c, row] = sum_m wp[c,m] x[row,m]; K=320, 10 phases.
// ---------------------------------------------------------------------------
__global__ __launch_bounds__(256, 1) void proj_mma_kernel(
    const __nv_bfloat16* __restrict__ xh, const __nv_bfloat16* __restrict__ xl,
    const __nv_bfloat16* __restrict__ wh, const __nv_bfloat16* __restrict__ wl,
    __nv_bfloat16* __restrict__ out_hi, __nv_bfloat16* __restrict__ out_lo)
{
    extern __shared__ char smem[];
    const uint32_t sb = smem_u32(smem);
    const int tid = threadIdx.x;
    const int wid = tid >> 5, lane = tid & 31;
    const int warp_m = wid >> 2, warp_n = wid & 3;
    const int rtile = blockIdx.x;        // row tile (256 rows)
    const int otile = blockIdx.y;        // c half

    float acc[4][8][4];
#pragma unroll
    for (int mi = 0; mi < 4; mi++)
#pragma unroll
        for (int ni = 0; ni < 8; ni++)
#pragma unroll
            for (int e = 0; e < 4; e++) acc[mi][ni][e] = 0.f;

    const int aRow = warp_m * 64 + (lane & 15);
    const int aCol = (lane >> 4) << 3;
    const int bRow = warp_n * 64 + ((lane & 7) | ((lane >> 4) << 3));
    const int bCol = ((lane >> 3) & 1) << 3;

    const int fr0 = tid >> 2;                  // 0..63
    const int fcB = (tid & 3) << 4;            // byte offset in row: 0,16,32,48

    auto fill = [&](int p, int s) {
        const int k0 = p * 32;
        const uint32_t st = sb + (uint32_t)s * STG_SZ;
#pragma unroll
        for (int rr = 0; rr < 2; rr++) {       // A: 128 rows
            const int r = fr0 + rr * 64;
            const uint32_t sdst = (uint32_t)(r * LDA * 2) + fcB;
            const size_t gA = (size_t)(otile * 128 + r) * KPADP + k0 + (fcB >> 1);
            cp16(st + sdst, wh + gA, 16);
            cp16(st + ABUF + sdst, wl + gA, 16);
        }
#pragma unroll
        for (int rr = 0; rr < 4; rr++) {       // B: 256 rows
            const int r = fr0 + rr * 64;
            const uint32_t sdst = (uint32_t)(r * LDA * 2) + fcB;
            const size_t gB = ((size_t)rtile * 256 + r) * KPADP + k0 + (fcB >> 1);
            cp16(st + 2 * ABUF + sdst, xh + gB, 16);
            cp16(st + 2 * ABUF + BBUF + sdst, xl + gB, 16);
        }
        cp_commit();
    };

    fill(0, 0);
#pragma unroll 1
    for (int p = 0; p < 10; p++) {
        const int s = p & 1;
        if (p + 1 < 10) { fill(p + 1, s ^ 1); cp_wait1(); }
        else            { cp_wait0(); }
        __syncthreads();
        const uint32_t st = sb + (uint32_t)s * STG_SZ;
#pragma unroll
        for (int ks = 0; ks < 2; ks++) {
            uint32_t ah[4][4], al[4][4];
#pragma unroll
            for (int mi = 0; mi < 4; mi++) {
                const uint32_t off = (uint32_t)(((aRow + mi * 16) * LDA) + aCol + ks * 16) * 2;
                ldsm_x4(ah[mi], st + off);
                ldsm_x4(al[mi], st + ABUF + off);
            }
#pragma unroll
            for (int bi = 0; bi < 4; bi++) {
                uint32_t bh[4], bl[4];
                const uint32_t off = (uint32_t)(((bRow + bi * 16) * LDA) + bCol + ks * 16) * 2;
                ldsm_x4(bh, st + 2 * ABUF + off);
                ldsm_x4(bl, st + 2 * ABUF + BBUF + off);
#pragma unroll
                for (int mi = 0; mi < 4; mi++)
#pragma unroll
                    for (int e2 = 0; e2 < 2; e2++) {
                        mma_16816(acc[mi][bi * 2 + e2], ah[mi], &bh[e2 * 2]);
                        mma_16816(acc[mi][bi * 2 + e2], ah[mi], &bl[e2 * 2]);
                        mma_16816(acc[mi][bi * 2 + e2], al[mi], &bh[e2 * 2]);
                    }
            }
        }
        __syncthreads();
    }

    // epilogue in two 128-l halves (smem reused as [128 l][136 c] bf16 hi/lo)
    __nv_bfloat16* stage_hi = (__nv_bfloat16*)smem;
    __nv_bfloat16* stage_lo = (__nv_bfloat16*)(smem + 34816);
    const int g = lane >> 2, tg = lane & 3;
#pragma unroll 1
    for (int h = 0; h < 2; h++) {
        if ((warp_n >> 1) == h) {
#pragma unroll
            for (int mi = 0; mi < 4; mi++) {
                const int row0 = warp_m * 64 + mi * 16 + g;
#pragma unroll
                for (int ni = 0; ni < 8; ni++) {
                    const int col = (warp_n & 1) * 64 + ni * 8 + tg * 2;  // l-local in half
#pragma unroll
                    for (int e = 0; e < 4; e++) {
                        const int row = row0 + ((e >> 1) << 3);           // c-local
                        const int c   = col + (e & 1);
                        __nv_bfloat16 hh, ll;
                        split_bf16(acc[mi][ni][e], hh, ll);
                        stage_hi[c * 136 + row] = hh;
                        stage_lo[c * 136 + row] = ll;
                    }
                }
            }
        }
        __syncthreads();
        {
            const int row  = tid >> 1;                          // l-local in half
            const int halfo = tid & 1;
            const char* sh = (const char*)stage_hi + row * 272 + halfo * 128;
            const char* sl = (const char*)stage_lo + row * 272 + halfo * 128;
            const size_t grow = (size_t)rtile * 256 + h * 128 + row;
            __nv_bfloat16* oh = out_hi + grow * HID + otile * 128 + halfo * 64;
            __nv_bfloat16* ol = out_lo + grow * HID + otile * 128 + halfo * 64;
#pragma unroll
            for (int k = 0; k < 8; k++) {
                ((uint4*)oh)[k] = ((const uint4*)sh)[k];
                ((uint4*)ol)[k] = ((const uint4*)sl)[k];
            }
        }
        __syncthreads();
    }
}

// ---------------------------------------------------------------------------
// Dilated conv layer via wide-tile pipelined mma (3-pass split bf16).
// 24 phases: tap t = p/8, i0 = (p%8)*32; shift applied at B fill, zero pad.
// CTA: 128 o x 256 l; grid (2 ltiles, 2 otiles, 256 chunks).
// ---------------------------------------------------------------------------
__global__ __launch_bounds__(256, 1) void conv_mma_kernel(
    const __nv_bfloat16* __restrict__ in_hi, const __nv_bfloat16* __restrict__ in_lo,
    const __nv_bfloat16* __restrict__ whi, const __nv_bfloat16* __restrict__ wlo,
    const float* __restrict__ bias,
    __nv_bfloat16* __restrict__ out_hi, __nv_bfloat16* __restrict__ out_lo, int d)
{
    extern __shared__ char smem[];
    const uint32_t sb = smem_u32(smem);
    const int tid = threadIdx.x;
    const int wid = tid >> 5, lane = tid & 31;
    const int warp_m = wid >> 2, warp_n = wid & 3;
    const int ltile = blockIdx.x, otile = blockIdx.y, n = blockIdx.z;

    const __nv_bfloat16* Hh = in_hi + (size_t)n * HLC;
    const __nv_bfloat16* Hl = in_lo + (size_t)n * HLC;

    float acc[4][8][4];
#pragma unroll
    for (int mi = 0; mi < 4; mi++)
#pragma unroll
        for (int ni = 0; ni < 8; ni++)
#pragma unroll
            for (int e = 0; e < 4; e++) acc[mi][ni][e] = 0.f;

    const int aRow = warp_m * 64 + (lane & 15);
    const int aCol = (lane >> 4) << 3;
    const int bRow = warp_n * 64 + ((lane & 7) | ((lane >> 4) << 3));
    const int bCol = ((lane >> 3) & 1) << 3;

    const int fr0 = tid >> 2;                  // 0..63
    const int fcB = (tid & 3) << 4;            // byte offset in row: 0,16,32,48

    auto fill = [&](int p, int s) {
        const int t  = p >> 3;
        const int i0 = (p & 7) * 32;
        const int shift = (t - 1) * d;
        const uint32_t st = sb + (uint32_t)s * STG_SZ;
#pragma unroll
        for (int rr = 0; rr < 2; rr++) {       // A: weight slice, 128 rows
            const int r = fr0 + rr * 64;
            const uint32_t sdst = (uint32_t)(r * LDA * 2) + fcB;
            const size_t gA = (size_t)t * WPLANE
                            + (size_t)(otile * 128 + r) * HID + i0 + (fcB >> 1);
            cp16(st + sdst, whi + gA, 16);
            cp16(st + ABUF + sdst, wlo + gA, 16);
        }
#pragma unroll
        for (int rr = 0; rr < 4; rr++) {       // B: shifted activations, 256 rows
            const int r = fr0 + rr * 64;
            const uint32_t sdst = (uint32_t)(r * LDA * 2) + fcB;
            const int lsrc = ltile * 256 + r + shift;
            const bool ok = (lsrc >= 0) && (lsrc < CHLEN);
            const size_t gB = (size_t)(ok ? lsrc : 0) * HID + i0 + (fcB >> 1);
            const int ssz = ok ? 16 : 0;
            cp16(st + 2 * ABUF + sdst, Hh + gB, ssz);
            cp16(st + 2 * ABUF + BBUF + sdst, Hl + gB, ssz);
        }
        cp_commit();
    };

    fill(0, 0);
#pragma unroll 1
    for (int p = 0; p < 24; p++) {
        const int s = p & 1;
        if (p + 1 < 24) { fill(p + 1, s ^ 1); cp_wait1(); }
        else            { cp_wait0(); }
        __syncthreads();
        const uint32_t st = sb + (uint32_t)s * STG_SZ;
#pragma unroll
        for (int ks = 0; ks < 2; ks++) {
            uint32_t ah[4][4], al[4][4];
#pragma unroll
            for (int mi = 0; mi < 4; mi++) {
                const uint32_t off = (uint32_t)(((aRow + mi * 16) * LDA) + aCol + ks * 16) * 2;
                ldsm_x4(ah[mi], st + off);
                ldsm_x4(al[mi], st + ABUF + off);
            }
#pragma unroll
            for (int bi = 0; bi < 4; bi++) {
                uint32_t bh[4], bl[4];
                const uint32_t off = (uint32_t)(((bRow + bi * 16) * LDA) + bCol + ks * 16) * 2;
                ldsm_x4(bh, st + 2 * ABUF + off);
                ldsm_x4(bl, st + 2 * ABUF + BBUF + off);
#pragma unroll
                for (int mi = 0; mi < 4; mi++)
#pragma unroll
                    for (int e2 = 0; e2 < 2; e2++) {
                        mma_16816(acc[mi][bi * 2 + e2], ah[mi], &bh[e2 * 2]);  // hi*hi
                        mma_16816(acc[mi][bi * 2 + e2], ah[mi], &bl[e2 * 2]);  // hi*lo
                        mma_16816(acc[mi][bi * 2 + e2], al[mi], &bh[e2 * 2]);  // lo*hi
                    }
            }
        }
        __syncthreads();
    }

    // epilogue: bias + exact gelu + residual, two 128-l halves
    __nv_bfloat16* stage_hi = (__nv_bfloat16*)smem;
    __nv_bfloat16* stage_lo = (__nv_bfloat16*)(smem + 34816);
    const int g = lane >> 2, tg = lane & 3;
#pragma unroll 1
    for (int h = 0; h < 2; h++) {
        if ((warp_n >> 1) == h) {
#pragma unroll
            for (int mi = 0; mi < 4; mi++) {
                const int row0 = warp_m * 64 + mi * 16 + g;
                const float b0 = bias[otile * 128 + row0];
                const float b8 = bias[otile * 128 + row0 + 8];
#pragma unroll
                for (int ni = 0; ni < 8; ni++) {
                    const int col = (warp_n & 1) * 64 + ni * 8 + tg * 2;  // l-local in half
#pragma unroll
                    for (int e = 0; e < 4; e++) {
                        const int row = row0 + ((e >> 1) << 3);           // o-local
                        const int c   = col + (e & 1);
                        float v = acc[mi][ni][e] + ((e < 2) ? b0 : b8);
                        float r = fmaf(v, normcdff(v), v);                // gelu(v) + v
                        __nv_bfloat16 hh, ll;
                        split_bf16(r, hh, ll);
                        stage_hi[c * 136 + row] = hh;
                        stage_lo[c * 136 + row] = ll;
                    }
                }
            }
        }
        __syncthreads();
        {
            const int row  = tid >> 1;                          // l-local in half
            const int halfo = tid & 1;
            const char* sh = (const char*)stage_hi + row * 272 + halfo * 128;
            const char* sl = (const char*)stage_lo + row * 272 + halfo * 128;
            const size_t lrow = (size_t)(ltile * 256 + h * 128 + row);
            __nv_bfloat16* oh = out_hi + (size_t)n * HLC + lrow * HID + otile * 128 + halfo * 64;
            __nv_bfloat16* ol = out_lo + (size_t)n * HLC + lrow * HID + otile * 128 + halfo * 64;
#pragma unroll
            for (int k = 0; k < 8; k++) {
                ((uint4*)oh)[k] = ((const uint4*)sh)[k];
                ((uint4*)ol)[k] = ((const uint4*)sl)[k];
            }
        }
        __syncthreads();
    }
}

// ---------------------------------------------------------------------------
// Profile head, [l][c] layout: out[l] = b + sum_k sum_c w[c][k] h[l+k-9][c]
// ---------------------------------------------------------------------------
#define PROF_Q_ROWS 531
#define PROF_SMEM   (PROF_Q_ROWS * 20 * 4 + 16 + HID * 20 * 4)

__global__ __launch_bounds__(256) void profile_head_kernel(
    const __nv_bfloat16* __restrict__ in_hi, const __nv_bfloat16* __restrict__ in_lo,
    const float* __restrict__ wprof, const float* __restrict__ bprof,
    float* __restrict__ out)
{
    extern __shared__ char smem[];
    float* Qs  = (float*)smem;                         // [531][20]
    float* wsh = (float*)(smem + PROF_Q_ROWS * 20 * 4 + 16);
    const int n = blockIdx.x, tid = threadIdx.x;
    const int wid = tid >> 5, lane = tid & 31;

    for (int i = tid; i < HID * 20; i += 256) wsh[i] = wprof[i];
    for (int i = tid; i < PROF_Q_ROWS * 20; i += 256) Qs[i] = 0.f;
    __syncthreads();

    const __nv_bfloat16* Hh = in_hi + (size_t)n * HLC;
    const __nv_bfloat16* Hl = in_lo + (size_t)n * HLC;
    for (int row = wid; row < CHLEN; row += 8) {
        uint4 uh = *(const uint4*)(Hh + (size_t)row * HID + lane * 8);
        uint4 ul = *(const uint4*)(Hl + (size_t)row * HID + lane * 8);
        const __nv_bfloat16* ph = (const __nv_bfloat16*)&uh;
        const __nv_bfloat16* pl = (const __nv_bfloat16*)&ul;
        float acc[20];
#pragma unroll
        for (int k = 0; k < 20; k++) acc[k] = 0.f;
#pragma unroll
        for (int cc = 0; cc < 8; cc++) {
            float hv = __bfloat162float(ph[cc]) + __bfloat162float(pl[cc]);
            const float* wr = &wsh[(lane * 8 + cc) * 20];
#pragma unroll
            for (int k = 0; k < 20; k++) acc[k] = fmaf(hv, wr[k], acc[k]);
        }
#pragma unroll
        for (int off = 16; off > 0; off >>= 1)
#pragma unroll
            for (int k = 0; k < 20; k++)
                acc[k] += __shfl_xor_sync(0xFFFFFFFF, acc[k], off);
        if (lane < 20) Qs[(row + 9) * 20 + lane] = acc[lane];
    }
    __syncthreads();

    const float bz = bprof[0];
    for (int l = tid; l < CHLEN; l += 256) {
        float s = bz;
#pragma unroll
        for (int k = 0; k < 20; k++) s += Qs[(l + k) * 20 + k];
        out[NCHUNK + (size_t)n * CHLEN + l] = s;
    }
}

// ---------------------------------------------------------------------------
// atpm head, [l][c] layout; n_peaks is int32 (JAX x64-disabled)
// ---------------------------------------------------------------------------
__global__ __launch_bounds__(256) void atpm_head_kernel(
    const __nv_bfloat16* __restrict__ in_hi, const __nv_bfloat16* __restrict__ in_lo,
    const float* __restrict__ watpm, const float* __restrict__ batpm,
    const int* __restrict__ npeaks, float* __restrict__ out)
{
    __shared__ float red[256];
    const int n = blockIdx.x, tid = threadIdx.x;
    const __nv_bfloat16* Hh = in_hi + (size_t)n * HLC + tid;
    const __nv_bfloat16* Hl = in_lo + (size_t)n * HLC + tid;
    float s = 0.f;
    for (int l = 0; l < CHLEN; l++)
        s += __bfloat162float(Hh[(size_t)l * HID]) + __bfloat162float(Hl[(size_t)l * HID]);
    red[tid] = s * watpm[tid];
    __syncthreads();
    for (int off = 128; off > 0; off >>= 1) {
        if (tid < off) red[tid] += red[tid + off];
        __syncthreads();
    }
    if (tid == 0) {
        float v = red[0] * (1.f / (float)CHLEN) + batpm[0];
        int b = n >> 7, p = n & 127;
        out[n] = (p < npeaks[b]) ? v : 0.f;
    }
}

// ---------------------------------------------------------------------------
extern "C" void kernel_launch(void* const* d_in, const int* in_sizes, int n_in,
                              void* d_out, int out_size)
{
    const float* x       = (const float*)d_in[0];
    const float* w_proj  = (const float*)d_in[1];
    const float* tower_w = (const float*)d_in[2];
    const float* tower_b = (const float*)d_in[3];
    const float* w_prof  = (const float*)d_in[4];
    const float* b_prof  = (const float*)d_in[5];
    const float* w_atpm  = (const float*)d_in[6];
    const float* b_atpm  = (const float*)d_in[7];
    const int*   n_peaks = (const int*)d_in[8];
    float* out = (float*)d_out;

    __nv_bfloat16 *hiA, *loA, *hiB, *loB, *wHi, *wLo, *xHi, *xLo, *wpHi, *wpLo;
    cudaGetSymbolAddress((void**)&hiA, g_hiA);
    cudaGetSymbolAddress((void**)&loA, g_loA);
    cudaGetSymbolAddress((void**)&hiB, g_hiB);
    cudaGetSymbolAddress((void**)&loB, g_loB);
    cudaGetSymbolAddress((void**)&wHi, g_wHi);
    cudaGetSymbolAddress((void**)&wLo, g_wLo);
    cudaGetSymbolAddress((void**)&xHi, g_xHi);
    cudaGetSymbolAddress((void**)&xLo, g_xLo);
    cudaGetSymbolAddress((void**)&wpHi, g_wpHi);
    cudaGetSymbolAddress((void**)&wpLo, g_wpLo);

    cudaFuncSetAttribute(conv_mma_kernel,
                         cudaFuncAttributeMaxDynamicSharedMemorySize, SM_PIPE);
    cudaFuncSetAttribute(proj_mma_kernel,
                         cudaFuncAttributeMaxDynamicSharedMemorySize, SM_PIPE);
    cudaFuncSetAttribute(profile_head_kernel,
                         cudaFuncAttributeMaxDynamicSharedMemorySize, PROF_SMEM);

    wprep_kernel<<<DEPTH * 3 * WPLANE / 256, 256>>>(tower_w, wHi, wLo);
    wpsplit_kernel<<<HID, 256>>>(w_proj, wpHi, wpLo);
    xsplit_kernel<<<NROWS, 256>>>(x, xHi, xLo);
    proj_mma_kernel<<<dim3(NROWS / 256, 2), 256, SM_PIPE>>>(xHi, xLo, wpHi, wpLo, hiA, loA);

    __nv_bfloat16 *ch = hiA, *cl = loA, *nh = hiB, *nl = loB;
    for (int i = 0; i < DEPTH; i++) {
        int d = 2 << i;          // 2^(i+1)
        conv_mma_kernel<<<dim3(2, 2, NCHUNK), 256, SM_PIPE>>>(
            ch, cl, wHi + (size_t)i * 3 * WPLANE, wLo + (size_t)i * 3 * WPLANE,
            tower_b + i * HID, nh, nl, d);
        __nv_bfloat16* t;
        t = ch; ch = nh; nh = t;
        t = cl; cl = nl; nl = t;
    }

    profile_head_kernel<<<NCHUNK, 256, PROF_SMEM>>>(ch, cl, w_prof, b_prof, out);
    atpm_head_kernel<<<NCHUNK, 256>>>(ch, cl, w_atpm, b_atpm, n_peaks, out);
}

// round 12
// speedup vs baseline: 1.4268x; 1.4268x over previous
#include <cuda_runtime.h>
#include <cuda_bf16.h>
#include <cstdint>

// Problem constants
#define NCHUNK  256            // BATCH * NPEAK
#define CHLEN   512
#define HID     256
#define MDIM    283
#define KPADP   320            // proj K padded to 5*64
#define DEPTH   7
#define HLC     131072         // CHLEN * HID elements per chunk, [l][c] layout
#define NROWS   131072         // total l rows (NCHUNK * CHLEN)
#define BUF_ELEMS ((size_t)NCHUNK * HLC)

// Activation ping-pong buffers, split bf16 (hi + lo reconstructs fp32 to ~2^-18)
__device__ __nv_bfloat16 g_hiA[BUF_ELEMS];
__device__ __nv_bfloat16 g_loA[BUF_ELEMS];
__device__ __nv_bfloat16 g_hiB[BUF_ELEMS];
__device__ __nv_bfloat16 g_loB[BUF_ELEMS];

// Pre-split tower weights: [layer][tap][o][i], bf16 hi/lo
#define WPLANE 65536                               // 256*256 per (layer,tap)
__device__ __nv_bfloat16 g_wHi[DEPTH * 3 * WPLANE];
__device__ __nv_bfloat16 g_wLo[DEPTH * 3 * WPLANE];

// Pre-split x and w_proj, K padded to 320
__device__ __nv_bfloat16 g_xHi[(size_t)NROWS * KPADP];
__device__ __nv_bfloat16 g_xLo[(size_t)NROWS * KPADP];
__device__ __nv_bfloat16 g_wpHi[HID * KPADP];
__device__ __nv_bfloat16 g_wpLo[HID * KPADP];

__device__ __forceinline__ uint32_t smem_u32(const void* p) {
    uint32_t a;
    asm("{ .reg .u64 t; cvta.to.shared.u64 t, %1; cvt.u32.u64 %0, t; }" : "=r"(a) : "l"(p));
    return a;
}
__device__ __forceinline__ void split_bf16(float v, __nv_bfloat16& h, __nv_bfloat16& l) {
    h = __float2bfloat16(v);
    l = __float2bfloat16(v - __bfloat162float(h));
}
__device__ __forceinline__ void ldsm_x4(uint32_t* r, uint32_t addr) {
    asm volatile("ldmatrix.sync.aligned.m8n8.x4.shared.b16 {%0,%1,%2,%3}, [%4];"
        : "=r"(r[0]), "=r"(r[1]), "=r"(r[2]), "=r"(r[3]) : "r"(addr));
}
__device__ __forceinline__ void mma_16816(float* d, const uint32_t* a, const uint32_t* b) {
    asm volatile("mma.sync.aligned.m16n8k16.row.col.f32.bf16.bf16.f32 "
        "{%0,%1,%2,%3},{%4,%5,%6,%7},{%8,%9},{%0,%1,%2,%3};"
        : "+f"(d[0]), "+f"(d[1]), "+f"(d[2]), "+f"(d[3])
        : "r"(a[0]), "r"(a[1]), "r"(a[2]), "r"(a[3]), "r"(b[0]), "r"(b[1]));
}
__device__ __forceinline__ void cp16(uint32_t dst, const void* src, int srcsize) {
    asm volatile("cp.async.cg.shared.global [%0], [%1], 16, %2;"
                 :: "r"(dst), "l"(src), "r"(srcsize) : "memory");
}
__device__ __forceinline__ void cp_commit_wait() {
    asm volatile("cp.async.commit_group;" ::: "memory");
    asm volatile("cp.async.wait_group 0;" ::: "memory");
}

// ---------------------------------------------------------------------------
// Prep kernels
// ---------------------------------------------------------------------------
__global__ __launch_bounds__(256) void wprep_kernel(
    const float* __restrict__ w, __nv_bfloat16* __restrict__ whi,
    __nv_bfloat16* __restrict__ wlo)
{
    size_t j = (size_t)blockIdx.x * 256 + threadIdx.x;     // < DEPTH*3*WPLANE
    int layer = (int)(j / (3 * WPLANE));
    int rem   = (int)(j % (3 * WPLANE));
    int t  = rem / WPLANE;
    int oi = rem % WPLANE;                                  // o*256 + i
    float v = w[(size_t)layer * 3 * WPLANE + (size_t)oi * 3 + t];
    __nv_bfloat16 h, l;
    split_bf16(v, h, l);
    whi[j] = h;
    wlo[j] = l;
}

__global__ __launch_bounds__(256) void xsplit_kernel(
    const float* __restrict__ x, __nv_bfloat16* __restrict__ xh,
    __nv_bfloat16* __restrict__ xl)
{
    const size_t row = blockIdx.x;                          // < NROWS
    for (int m = threadIdx.x; m < KPADP; m += 256) {
        float v = (m < MDIM) ? x[row * MDIM + m] : 0.f;
        __nv_bfloat16 h, l;
        split_bf16(v, h, l);
        xh[row * KPADP + m] = h;
        xl[row * KPADP + m] = l;
    }
}

__global__ __launch_bounds__(256) void wpsplit_kernel(
    const float* __restrict__ wp, __nv_bfloat16* __restrict__ wh,
    __nv_bfloat16* __restrict__ wl)
{
    const size_t c = blockIdx.x;                            // < HID
    for (int m = threadIdx.x; m < KPADP; m += 256) {
        float v = (m < MDIM) ? wp[c * MDIM + m] : 0.f;
        __nv_bfloat16 h, l;
        split_bf16(v, h, l);
        wh[c * KPADP + m] = h;
        wl[c * KPADP + m] = l;
    }
}

// ---------------------------------------------------------------------------
// Shared mma tile geometry (R7 winner config).
// CTA: 128 M x 128 N; 8 warps (2x4), warp tile 64x32; phase K=64.
// SMEM per phase: A hi/lo + B hi/lo, each 128 x 64 bf16 with LDA=72 pad.
// Total 73728 B -> 2 CTAs/SM.
// MMA pass order: pass-OUTER (all 16 accs per pass) so no back-to-back
// RAW chains on the same accumulator.
// ---------------------------------------------------------------------------
#define LDA     72
#define ABUF    18432
#define SM_MMA  73728

// ---------------------------------------------------------------------------
// Projection via mma: D[c, row] = sum_m wp[c,m] x[row,m]; K=320, 5 phases.
// ---------------------------------------------------------------------------
__global__ __launch_bounds__(256, 2) void proj_mma_kernel(
    const __nv_bfloat16* __restrict__ xh, const __nv_bfloat16* __restrict__ xl,
    const __nv_bfloat16* __restrict__ wh, const __nv_bfloat16* __restrict__ wl,
    __nv_bfloat16* __restrict__ out_hi, __nv_bfloat16* __restrict__ out_lo)
{
    extern __shared__ char smem[];
    const uint32_t sb = smem_u32(smem);
    const uint32_t sbAh = sb, sbAl = sb + ABUF, sbBh = sb + 2 * ABUF, sbBl = sb + 3 * ABUF;
    const int tid = threadIdx.x;
    const int wid = tid >> 5, lane = tid & 31;
    const int warp_m = wid >> 2, warp_n = wid & 3;
    const int rtile = blockIdx.x;        // row tile (128 rows)
    const int otile = blockIdx.y;        // c half

    float acc[4][4][4];
#pragma unroll
    for (int mi = 0; mi < 4; mi++)
#pragma unroll
        for (int ni = 0; ni < 4; ni++)
#pragma unroll
            for (int e = 0; e < 4; e++) acc[mi][ni][e] = 0.f;

    const int aRow = warp_m * 64 + (lane & 15);
    const int aCol = (lane >> 4) << 3;
    const int bRow = warp_n * 32 + ((lane & 7) | ((lane >> 4) << 3));
    const int bCol = ((lane >> 3) & 1) << 3;

#pragma unroll 1
    for (int k0 = 0; k0 < KPADP; k0 += 64) {
        __syncthreads();
        for (int idx = tid; idx < 1024; idx += 256) {
            const int r = idx >> 3, ch = idx & 7;
            const size_t gsrc = (size_t)(otile * 128 + r) * KPADP + k0 + ch * 8;
            const uint32_t sdst = (uint32_t)(r * LDA + ch * 8) * 2;
            cp16(sbAh + sdst, wh + gsrc, 16);
            cp16(sbAl + sdst, wl + gsrc, 16);
        }
        for (int idx = tid; idx < 1024; idx += 256) {
            const int r = idx >> 3, ch = idx & 7;
            const size_t gsrc = ((size_t)rtile * 128 + r) * KPADP + k0 + ch * 8;
            const uint32_t sdst = (uint32_t)(r * LDA + ch * 8) * 2;
            cp16(sbBh + sdst, xh + gsrc, 16);
            cp16(sbBl + sdst, xl + gsrc, 16);
        }
        cp_commit_wait();
        __syncthreads();
#pragma unroll
        for (int ks = 0; ks < 4; ks++) {
            uint32_t ah[4][4], al[4][4], bh[8], bl[8];
#pragma unroll
            for (int mi = 0; mi < 4; mi++) {
                const uint32_t off = (uint32_t)(((aRow + mi * 16) * LDA) + aCol + ks * 16) * 2;
                ldsm_x4(ah[mi], sbAh + off);
                ldsm_x4(al[mi], sbAl + off);
            }
#pragma unroll
            for (int bi = 0; bi < 2; bi++) {
                const uint32_t off = (uint32_t)(((bRow + bi * 16) * LDA) + bCol + ks * 16) * 2;
                ldsm_x4(&bh[bi * 4], sbBh + off);
                ldsm_x4(&bl[bi * 4], sbBl + off);
            }
            // pass-outer: 16 independent accs between reuses (no RAW chains)
#pragma unroll
            for (int mi = 0; mi < 4; mi++)
#pragma unroll
                for (int ni = 0; ni < 4; ni++)
                    mma_16816(acc[mi][ni], ah[mi], &bh[ni * 2]);   // hi*hi
#pragma unroll
            for (int mi = 0; mi < 4; mi++)
#pragma unroll
                for (int ni = 0; ni < 4; ni++)
                    mma_16816(acc[mi][ni], ah[mi], &bl[ni * 2]);   // hi*lo
#pragma unroll
            for (int mi = 0; mi < 4; mi++)
#pragma unroll
                for (int ni = 0; ni < 4; ni++)
                    mma_16816(acc[mi][ni], al[mi], &bh[ni * 2]);   // lo*hi
        }
    }

    // epilogue: transpose-stage, split store
    __syncthreads();
    __nv_bfloat16* stage_hi = (__nv_bfloat16*)smem;            // [128 l][136 c]
    __nv_bfloat16* stage_lo = (__nv_bfloat16*)(smem + 36864);
    const int g = lane >> 2, tg = lane & 3;
#pragma unroll
    for (int mi = 0; mi < 4; mi++) {
        const int row0 = warp_m * 64 + mi * 16 + g;
#pragma unroll
        for (int ni = 0; ni < 4; ni++) {
            const int col = warp_n * 32 + ni * 8 + tg * 2;
#pragma unroll
            for (int e = 0; e < 4; e++) {
                const int row = row0 + ((e >> 1) << 3);        // c-local
                const int c   = col + (e & 1);                 // l-local
                __nv_bfloat16 h, l;
                split_bf16(acc[mi][ni][e], h, l);
                stage_hi[c * 136 + row] = h;
                stage_lo[c * 136 + row] = l;
            }
        }
    }
    __syncthreads();
    {
        const int row  = tid >> 1;                              // l-local
        const int half = tid & 1;
        const char* sh = (const char*)stage_hi + row * 272 + half * 128;
        const char* sl = (const char*)stage_lo + row * 272 + half * 128;
        const size_t grow = (size_t)rtile * 128 + row;          // global l row
        __nv_bfloat16* oh = out_hi + grow * HID + otile * 128 + half * 64;
        __nv_bfloat16* ol = out_lo + grow * HID + otile * 128 + half * 64;
#pragma unroll
        for (int k = 0; k < 8; k++) {
            ((uint4*)oh)[k] = ((const uint4*)sh)[k];
            ((uint4*)ol)[k] = ((const uint4*)sl)[k];
        }
    }
}

// ---------------------------------------------------------------------------
// Dilated conv layer via mma.sync bf16 split-precision (3 passes).
// 12 phases (tap outer, i-chunk of 64 inner), single-buffered -> 2 CTA/SM.
// ---------------------------------------------------------------------------
__global__ __launch_bounds__(256, 2) void conv_mma_kernel(
    const __nv_bfloat16* __restrict__ in_hi, const __nv_bfloat16* __restrict__ in_lo,
    const __nv_bfloat16* __restrict__ whi, const __nv_bfloat16* __restrict__ wlo,
    const float* __restrict__ bias,
    __nv_bfloat16* __restrict__ out_hi, __nv_bfloat16* __restrict__ out_lo, int d)
{
    extern __shared__ char smem[];
    const uint32_t sb = smem_u32(smem);
    const uint32_t sbAh = sb, sbAl = sb + ABUF, sbBh = sb + 2 * ABUF, sbBl = sb + 3 * ABUF;
    const int tid = threadIdx.x;
    const int wid = tid >> 5, lane = tid & 31;
    const int warp_m = wid >> 2, warp_n = wid & 3;
    const int ltile = blockIdx.x, otile = blockIdx.y, n = blockIdx.z;

    const __nv_bfloat16* Hh = in_hi + (size_t)n * HLC;
    const __nv_bfloat16* Hl = in_lo + (size_t)n * HLC;

    float acc[4][4][4];
#pragma unroll
    for (int mi = 0; mi < 4; mi++)
#pragma unroll
        for (int ni = 0; ni < 4; ni++)
#pragma unroll
            for (int e = 0; e < 4; e++) acc[mi][ni][e] = 0.f;

    const int aRow = warp_m * 64 + (lane & 15);
    const int aCol = (lane >> 4) << 3;
    const int bRow = warp_n * 32 + ((lane & 7) | ((lane >> 4) << 3));
    const int bCol = ((lane >> 3) & 1) << 3;

#pragma unroll 1
    for (int t = 0; t < 3; t++) {
        const int shift = (t - 1) * d;
#pragma unroll 1
        for (int i0 = 0; i0 < HID; i0 += 64) {
            __syncthreads();                   // prior phase's ldsm done
            // A: weight slice [128 o][64 i] hi/lo
            for (int idx = tid; idx < 1024; idx += 256) {
                const int r = idx >> 3, ch = idx & 7;
                const size_t gsrc = (size_t)t * WPLANE
                                  + (size_t)(otile * 128 + r) * HID + i0 + ch * 8;
                const uint32_t sdst = (uint32_t)(r * LDA + ch * 8) * 2;
                cp16(sbAh + sdst, whi + gsrc, 16);
                cp16(sbAl + sdst, wlo + gsrc, 16);
            }
            // B: shifted activation slice [128 l][64 i] hi/lo, zero-padded
            for (int idx = tid; idx < 1024; idx += 256) {
                const int r = idx >> 3, ch = idx & 7;
                const int lsrc = ltile * 128 + r + shift;
                const bool ok = (lsrc >= 0) && (lsrc < CHLEN);
                const size_t goff = (size_t)(ok ? lsrc : 0) * HID + i0 + ch * 8;
                const int ssz = ok ? 16 : 0;
                const uint32_t sdst = SM_MMA * 0 + (uint32_t)(r * LDA + ch * 8) * 2;
                cp16(sbBh + sdst, Hh + goff, ssz);
                cp16(sbBl + sdst, Hl + goff, ssz);
            }
            cp_commit_wait();
            __syncthreads();
#pragma unroll
            for (int ks = 0; ks < 4; ks++) {
                uint32_t ah[4][4], al[4][4], bh[8], bl[8];
#pragma unroll
                for (int mi = 0; mi < 4; mi++) {
                    const uint32_t off = (uint32_t)(((aRow + mi * 16) * LDA) + aCol + ks * 16) * 2;
                    ldsm_x4(ah[mi], sbAh + off);
                    ldsm_x4(al[mi], sbAl + off);
                }
#pragma unroll
                for (int bi = 0; bi < 2; bi++) {
                    const uint32_t off = (uint32_t)(((bRow + bi * 16) * LDA) + bCol + ks * 16) * 2;
                    ldsm_x4(&bh[bi * 4], sbBh + off);
                    ldsm_x4(&bl[bi * 4], sbBl + off);
                }
                // pass-outer: 16 independent accs between reuses (no RAW chains)
#pragma unroll
                for (int mi = 0; mi < 4; mi++)
#pragma unroll
                    for (int ni = 0; ni < 4; ni++)
                        mma_16816(acc[mi][ni], ah[mi], &bh[ni * 2]);   // hi*hi
#pragma unroll
                for (int mi = 0; mi < 4; mi++)
#pragma unroll
                    for (int ni = 0; ni < 4; ni++)
                        mma_16816(acc[mi][ni], ah[mi], &bl[ni * 2]);   // hi*lo
#pragma unroll
                for (int mi = 0; mi < 4; mi++)
#pragma unroll
                    for (int ni = 0; ni < 4; ni++)
                        mma_16816(acc[mi][ni], al[mi], &bh[ni * 2]);   // lo*hi
            }
        }
    }

    // ---- epilogue: bias + exact gelu + residual, stage [l][o], split store
    __syncthreads();
    __nv_bfloat16* stage_hi = (__nv_bfloat16*)smem;            // [128 l][136 o]
    __nv_bfloat16* stage_lo = (__nv_bfloat16*)(smem + 36864);
    const int g = lane >> 2, tg = lane & 3;
#pragma unroll
    for (int mi = 0; mi < 4; mi++) {
        const int row0 = warp_m * 64 + mi * 16 + g;
        const float b0 = bias[otile * 128 + row0];
        const float b8 = bias[otile * 128 + row0 + 8];
#pragma unroll
        for (int ni = 0; ni < 4; ni++) {
            const int col = warp_n * 32 + ni * 8 + tg * 2;
#pragma unroll
            for (int e = 0; e < 4; e++) {
                const int row = row0 + ((e >> 1) << 3);
                const int c   = col + (e & 1);
                float v = acc[mi][ni][e] + ((e < 2) ? b0 : b8);
                float r = fmaf(v, normcdff(v), v);             // gelu(v) + v
                __nv_bfloat16 h, l;
                split_bf16(r, h, l);
                stage_hi[c * 136 + row] = h;
                stage_lo[c * 136 + row] = l;
            }
        }
    }
    __syncthreads();
    {
        const int row  = tid >> 1;                              // l-local
        const int half = tid & 1;                               // o 64-half
        const char* sh = (const char*)stage_hi + row * 272 + half * 128;
        const char* sl = (const char*)stage_lo + row * 272 + half * 128;
        __nv_bfloat16* oh = out_hi + (size_t)n * HLC +
                            (size_t)(ltile * 128 + row) * HID + otile * 128 + half * 64;
        __nv_bfloat16* ol = out_lo + (size_t)n * HLC +
                            (size_t)(ltile * 128 + row) * HID + otile * 128 + half * 64;
#pragma unroll
        for (int k = 0; k < 8; k++) {
            ((uint4*)oh)[k] = ((const uint4*)sh)[k];
            ((uint4*)ol)[k] = ((const uint4*)sl)[k];
        }
    }
}

// ---------------------------------------------------------------------------
// Profile head, [l][c] layout: out[l] = b + sum_k sum_c w[c][k] h[l+k-9][c]
// ---------------------------------------------------------------------------
#define PROF_Q_ROWS 531
#define PROF_SMEM   (PROF_Q_ROWS * 20 * 4 + 16 + HID * 20 * 4)

__global__ __launch_bounds__(256) void profile_head_kernel(
    const __nv_bfloat16* __restrict__ in_hi, const __nv_bfloat16* __restrict__ in_lo,
    const float* __restrict__ wprof, const float* __restrict__ bprof,
    float* __restrict__ out)
{
    extern __shared__ char smem[];
    float* Qs  = (float*)smem;                         // [531][20]
    float* wsh = (float*)(smem + PROF_Q_ROWS * 20 * 4 + 16);
    const int n = blockIdx.x, tid = threadIdx.x;
    const int wid = tid >> 5, lane = tid & 31;

    for (int i = tid; i < HID * 20; i += 256) wsh[i] = wprof[i];
    for (int i = tid; i < PROF_Q_ROWS * 20; i += 256) Qs[i] = 0.f;
    __syncthreads();

    const __nv_bfloat16* Hh = in_hi + (size_t)n * HLC;
    const __nv_bfloat16* Hl = in_lo + (size_t)n * HLC;
    for (int row = wid; row < CHLEN; row += 8) {
        uint4 uh = *(const uint4*)(Hh + (size_t)row * HID + lane * 8);
        uint4 ul = *(const uint4*)(Hl + (size_t)row * HID + lane * 8);
        const __nv_bfloat16* ph = (const __nv_bfloat16*)&uh;
        const __nv_bfloat16* pl = (const __nv_bfloat16*)&ul;
        float acc[20];
#pragma unroll
        for (int k = 0; k < 20; k++) acc[k] = 0.f;
#pragma unroll
        for (int cc = 0; cc < 8; cc++) {
            float hv = __bfloat162float(ph[cc]) + __bfloat162float(pl[cc]);
            const float* wr = &wsh[(lane * 8 + cc) * 20];
#pragma unroll
            for (int k = 0; k < 20; k++) acc[k] = fmaf(hv, wr[k], acc[k]);
        }
#pragma unroll
        for (int off = 16; off > 0; off >>= 1)
#pragma unroll
            for (int k = 0; k < 20; k++)
                acc[k] += __shfl_xor_sync(0xFFFFFFFF, acc[k], off);
        if (lane < 20) Qs[(row + 9) * 20 + lane] = acc[lane];
    }
    __syncthreads();

    const float bz = bprof[0];
    for (int l = tid; l < CHLEN; l += 256) {
        float s = bz;
#pragma unroll
        for (int k = 0; k < 20; k++) s += Qs[(l + k) * 20 + k];
        out[NCHUNK + (size_t)n * CHLEN + l] = s;
    }
}

// ---------------------------------------------------------------------------
// atpm head, [l][c] layout; n_peaks is int32 (JAX x64-disabled)
// ---------------------------------------------------------------------------
__global__ __launch_bounds__(256) void atpm_head_kernel(
    const __nv_bfloat16* __restrict__ in_hi, const __nv_bfloat16* __restrict__ in_lo,
    const float* __restrict__ watpm, const float* __restrict__ batpm,
    const int* __restrict__ npeaks, float* __restrict__ out)
{
    __shared__ float red[256];
    const int n = blockIdx.x, tid = threadIdx.x;
    const __nv_bfloat16* Hh = in_hi + (size_t)n * HLC + tid;
    const __nv_bfloat16* Hl = in_lo + (size_t)n * HLC + tid;
    float s = 0.f;
    for (int l = 0; l < CHLEN; l++)
        s += __bfloat162float(Hh[(size_t)l * HID]) + __bfloat162float(Hl[(size_t)l * HID]);
    red[tid] = s * watpm[tid];
    __syncthreads();
    for (int off = 128; off > 0; off >>= 1) {
        if (tid < off) red[tid] += red[tid + off];
        __syncthreads();
    }
    if (tid == 0) {
        float v = red[0] * (1.f / (float)CHLEN) + batpm[0];
        int b = n >> 7, p = n & 127;
        out[n] = (p < npeaks[b]) ? v : 0.f;
    }
}

// ---------------------------------------------------------------------------
extern "C" void kernel_launch(void* const* d_in, const int* in_sizes, int n_in,
                              void* d_out, int out_size)
{
    const float* x       = (const float*)d_in[0];
    const float* w_proj  = (const float*)d_in[1];
    const float* tower_w = (const float*)d_in[2];
    const float* tower_b = (const float*)d_in[3];
    const float* w_prof  = (const float*)d_in[4];
    const float* b_prof  = (const float*)d_in[5];
    const float* w_atpm  = (const float*)d_in[6];
    const float* b_atpm  = (const float*)d_in[7];
    const int*   n_peaks = (const int*)d_in[8];
    float* out = (float*)d_out;

    __nv_bfloat16 *hiA, *loA, *hiB, *loB, *wHi, *wLo, *xHi, *xLo, *wpHi, *wpLo;
    cudaGetSymbolAddress((void**)&hiA, g_hiA);
    cudaGetSymbolAddress((void**)&loA, g_loA);
    cudaGetSymbolAddress((void**)&hiB, g_hiB);
    cudaGetSymbolAddress((void**)&loB, g_loB);
    cudaGetSymbolAddress((void**)&wHi, g_wHi);
    cudaGetSymbolAddress((void**)&wLo, g_wLo);
    cudaGetSymbolAddress((void**)&xHi, g_xHi);
    cudaGetSymbolAddress((void**)&xLo, g_xLo);
    cudaGetSymbolAddress((void**)&wpHi, g_wpHi);
    cudaGetSymbolAddress((void**)&wpLo, g_wpLo);

    cudaFuncSetAttribute(conv_mma_kernel,
                         cudaFuncAttributeMaxDynamicSharedMemorySize, SM_MMA);
    cudaFuncSetAttribute(proj_mma_kernel,
                         cudaFuncAttributeMaxDynamicSharedMemorySize, SM_MMA);
    cudaFuncSetAttribute(profile_head_kernel,
                         cudaFuncAttributeMaxDynamicSharedMemorySize, PROF_SMEM);

    wprep_kernel<<<DEPTH * 3 * WPLANE / 256, 256>>>(tower_w, wHi, wLo);
    wpsplit_kernel<<<HID, 256>>>(w_proj, wpHi, wpLo);
    xsplit_kernel<<<NROWS, 256>>>(x, xHi, xLo);
    proj_mma_kernel<<<dim3(NROWS / 128, 2), 256, SM_MMA>>>(xHi, xLo, wpHi, wpLo, hiA, loA);

    __nv_bfloat16 *ch = hiA, *cl = loA, *nh = hiB, *nl = loB;
    for (int i = 0; i < DEPTH; i++) {
        int d = 2 << i;          // 2^(i+1)
        conv_mma_kernel<<<dim3(4, 2, NCHUNK), 256, SM_MMA>>>(
            ch, cl, wHi + (size_t)i * 3 * WPLANE, wLo + (size_t)i * 3 * WPLANE,
            tower_b + i * HID, nh, nl, d);
        __nv_bfloat16* t;
        t = ch; ch = nh; nh = t;
        t = cl; cl = nl; nl = t;
    }

    profile_head_kernel<<<NCHUNK, 256, PROF_SMEM>>>(ch, cl, w_prof, b_prof, out);
    atpm_head_kernel<<<NCHUNK, 256>>>(ch, cl, w_atpm, b_atpm, n_peaks, out);
}

// round 13
// speedup vs baseline: 1.8762x; 1.3150x over previous
#include <cuda_runtime.h>
#include <cuda_fp16.h>
#include <cstdint>

// Problem constants
#define NCHUNK  256            // BATCH * NPEAK
#define CHLEN   512
#define HID     256
#define MDIM    283
#define KPADP   320            // proj K padded to 5*64
#define DEPTH   7
#define HLC     131072         // CHLEN * HID elements per chunk, [l][c] layout
#define NROWS   131072         // total l rows (NCHUNK * CHLEN)
#define BUF_ELEMS ((size_t)NCHUNK * HLC)

// Activation ping-pong buffers, split fp16 (hi + lo reconstructs fp32 to ~2^-22)
__device__ __half g_hiA[BUF_ELEMS];
__device__ __half g_loA[BUF_ELEMS];
__device__ __half g_hiB[BUF_ELEMS];
__device__ __half g_loB[BUF_ELEMS];

// Tower weights as single fp16 (11-bit mantissa, ~2^-12 rel err): [layer][tap][o][i]
#define WPLANE 65536                               // 256*256 per (layer,tap)
__device__ __half g_w16[DEPTH * 3 * WPLANE];

// x split fp16 hi/lo + w_proj single fp16, K padded to 320
__device__ __half g_xHi[(size_t)NROWS * KPADP];
__device__ __half g_xLo[(size_t)NROWS * KPADP];
__device__ __half g_wp16[HID * KPADP];

__device__ __forceinline__ uint32_t smem_u32(const void* p) {
    uint32_t a;
    asm("{ .reg .u64 t; cvta.to.shared.u64 t, %1; cvt.u32.u64 %0, t; }" : "=r"(a) : "l"(p));
    return a;
}
__device__ __forceinline__ void split_f16(float v, __half& h, __half& l) {
    h = __float2half_rn(v);
    l = __float2half_rn(v - __half2float(h));
}
__device__ __forceinline__ void ldsm_x4(uint32_t* r, uint32_t addr) {
    asm volatile("ldmatrix.sync.aligned.m8n8.x4.shared.b16 {%0,%1,%2,%3}, [%4];"
        : "=r"(r[0]), "=r"(r[1]), "=r"(r[2]), "=r"(r[3]) : "r"(addr));
}
__device__ __forceinline__ void mma_16816(float* d, const uint32_t* a, const uint32_t* b) {
    asm volatile("mma.sync.aligned.m16n8k16.row.col.f32.f16.f16.f32 "
        "{%0,%1,%2,%3},{%4,%5,%6,%7},{%8,%9},{%0,%1,%2,%3};"
        : "+f"(d[0]), "+f"(d[1]), "+f"(d[2]), "+f"(d[3])
        : "r"(a[0]), "r"(a[1]), "r"(a[2]), "r"(a[3]), "r"(b[0]), "r"(b[1]));
}
__device__ __forceinline__ void cp16(uint32_t dst, const void* src, int srcsize) {
    asm volatile("cp.async.cg.shared.global [%0], [%1], 16, %2;"
                 :: "r"(dst), "l"(src), "r"(srcsize) : "memory");
}
__device__ __forceinline__ void cp_commit_wait() {
    asm volatile("cp.async.commit_group;" ::: "memory");
    asm volatile("cp.async.wait_group 0;" ::: "memory");
}

// ---------------------------------------------------------------------------
// Prep kernels
// ---------------------------------------------------------------------------
__global__ __launch_bounds__(256) void wprep_kernel(
    const float* __restrict__ w, __half* __restrict__ w16)
{
    size_t j = (size_t)blockIdx.x * 256 + threadIdx.x;     // < DEPTH*3*WPLANE
    int layer = (int)(j / (3 * WPLANE));
    int rem   = (int)(j % (3 * WPLANE));
    int t  = rem / WPLANE;
    int oi = rem % WPLANE;                                  // o*256 + i
    float v = w[(size_t)layer * 3 * WPLANE + (size_t)oi * 3 + t];
    w16[j] = __float2half_rn(v);
}

__global__ __launch_bounds__(256) void xsplit_kernel(
    const float* __restrict__ x, __half* __restrict__ xh, __half* __restrict__ xl)
{
    const size_t row = blockIdx.x;                          // < NROWS
    for (int m = threadIdx.x; m < KPADP; m += 256) {
        float v = (m < MDIM) ? x[row * MDIM + m] : 0.f;
        __half h, l;
        split_f16(v, h, l);
        xh[row * KPADP + m] = h;
        xl[row * KPADP + m] = l;
    }
}

__global__ __launch_bounds__(256) void wpsplit_kernel(
    const float* __restrict__ wp, __half* __restrict__ w16)
{
    const size_t c = blockIdx.x;                            // < HID
    for (int m = threadIdx.x; m < KPADP; m += 256) {
        float v = (m < MDIM) ? wp[c * MDIM + m] : 0.f;
        w16[c * KPADP + m] = __float2half_rn(v);
    }
}

// ---------------------------------------------------------------------------
// MMA tile geometry (R7 occupancy config, fp16 2-pass).
// CTA: 128 M x 128 N; 8 warps (2x4), warp tile 64x32; phase K=64.
// SMEM per phase: A(single) + B hi/lo, each 128 x 64 fp16 with LDA=72 pad.
// 3 * 18432 = 55296 operand bytes; alloc 73728 (epilogue staging) -> 2 CTA/SM.
// ---------------------------------------------------------------------------
#define LDA     72
#define ABUF    18432
#define SM_MMA  73728

// ---------------------------------------------------------------------------
// Projection via mma: D[c, row] = sum_m wp[c,m] x[row,m]; K=320, 5 phases.
// ---------------------------------------------------------------------------
__global__ __launch_bounds__(256, 2) void proj_mma_kernel(
    const __half* __restrict__ xh, const __half* __restrict__ xl,
    const __half* __restrict__ w16,
    __half* __restrict__ out_hi, __half* __restrict__ out_lo)
{
    extern __shared__ char smem[];
    const uint32_t sb = smem_u32(smem);
    const uint32_t sbA = sb, sbBh = sb + ABUF, sbBl = sb + 2 * ABUF;
    const int tid = threadIdx.x;
    const int wid = tid >> 5, lane = tid & 31;
    const int warp_m = wid >> 2, warp_n = wid & 3;
    const int rtile = blockIdx.x;        // row tile (128 rows)
    const int otile = blockIdx.y;        // c half

    float acc[4][4][4];
#pragma unroll
    for (int mi = 0; mi < 4; mi++)
#pragma unroll
        for (int ni = 0; ni < 4; ni++)
#pragma unroll
            for (int e = 0; e < 4; e++) acc[mi][ni][e] = 0.f;

    const int aRow = warp_m * 64 + (lane & 15);
    const int aCol = (lane >> 4) << 3;
    const int bRow = warp_n * 32 + ((lane & 7) | ((lane >> 4) << 3));
    const int bCol = ((lane >> 3) & 1) << 3;

#pragma unroll 1
    for (int k0 = 0; k0 < KPADP; k0 += 64) {
        __syncthreads();
        for (int idx = tid; idx < 1024; idx += 256) {
            const int r = idx >> 3, ch = idx & 7;
            const size_t gsrc = (size_t)(otile * 128 + r) * KPADP + k0 + ch * 8;
            const uint32_t sdst = (uint32_t)(r * LDA + ch * 8) * 2;
            cp16(sbA + sdst, w16 + gsrc, 16);
        }
        for (int idx = tid; idx < 1024; idx += 256) {
            const int r = idx >> 3, ch = idx & 7;
            const size_t gsrc = ((size_t)rtile * 128 + r) * KPADP + k0 + ch * 8;
            const uint32_t sdst = (uint32_t)(r * LDA + ch * 8) * 2;
            cp16(sbBh + sdst, xh + gsrc, 16);
            cp16(sbBl + sdst, xl + gsrc, 16);
        }
        cp_commit_wait();
        __syncthreads();
#pragma unroll
        for (int ks = 0; ks < 4; ks++) {
            uint32_t a4[4][4], bh[8], bl[8];
#pragma unroll
            for (int mi = 0; mi < 4; mi++) {
                const uint32_t off = (uint32_t)(((aRow + mi * 16) * LDA) + aCol + ks * 16) * 2;
                ldsm_x4(a4[mi], sbA + off);
            }
#pragma unroll
            for (int bi = 0; bi < 2; bi++) {
                const uint32_t off = (uint32_t)(((bRow + bi * 16) * LDA) + bCol + ks * 16) * 2;
                ldsm_x4(&bh[bi * 4], sbBh + off);
                ldsm_x4(&bl[bi * 4], sbBl + off);
            }
#pragma unroll
            for (int mi = 0; mi < 4; mi++)
#pragma unroll
                for (int ni = 0; ni < 4; ni++)
                    mma_16816(acc[mi][ni], a4[mi], &bh[ni * 2]);   // W * Hhi
#pragma unroll
            for (int mi = 0; mi < 4; mi++)
#pragma unroll
                for (int ni = 0; ni < 4; ni++)
                    mma_16816(acc[mi][ni], a4[mi], &bl[ni * 2]);   // W * Hlo
        }
    }

    // epilogue: transpose-stage, split store
    __syncthreads();
    __half* stage_hi = (__half*)smem;            // [128 l][136 c]
    __half* stage_lo = (__half*)(smem + 36864);
    const int g = lane >> 2, tg = lane & 3;
#pragma unroll
    for (int mi = 0; mi < 4; mi++) {
        const int row0 = warp_m * 64 + mi * 16 + g;
#pragma unroll
        for (int ni = 0; ni < 4; ni++) {
            const int col = warp_n * 32 + ni * 8 + tg * 2;
#pragma unroll
            for (int e = 0; e < 4; e++) {
                const int row = row0 + ((e >> 1) << 3);        // c-local
                const int c   = col + (e & 1);                 // l-local
                __half h, l;
                split_f16(acc[mi][ni][e], h, l);
                stage_hi[c * 136 + row] = h;
                stage_lo[c * 136 + row] = l;
            }
        }
    }
    __syncthreads();
    {
        const int row  = tid >> 1;                              // l-local
        const int half = tid & 1;
        const char* sh = (const char*)stage_hi + row * 272 + half * 128;
        const char* sl = (const char*)stage_lo + row * 272 + half * 128;
        const size_t grow = (size_t)rtile * 128 + row;          // global l row
        __half* oh = out_hi + grow * HID + otile * 128 + half * 64;
        __half* ol = out_lo + grow * HID + otile * 128 + half * 64;
#pragma unroll
        for (int k = 0; k < 8; k++) {
            ((uint4*)oh)[k] = ((const uint4*)sh)[k];
            ((uint4*)ol)[k] = ((const uint4*)sl)[k];
        }
    }
}

// ---------------------------------------------------------------------------
// Dilated conv layer via mma.sync fp16 2-pass (W fp16, H split hi/lo).
// 12 phases (tap outer, i-chunk of 64 inner), single-buffered -> 2 CTA/SM.
// ---------------------------------------------------------------------------
__global__ __launch_bounds__(256, 2) void conv_mma_kernel(
    const __half* __restrict__ in_hi, const __half* __restrict__ in_lo,
    const __half* __restrict__ w16, const float* __restrict__ bias,
    __half* __restrict__ out_hi, __half* __restrict__ out_lo, int d)
{
    extern __shared__ char smem[];
    const uint32_t sb = smem_u32(smem);
    const uint32_t sbA = sb, sbBh = sb + ABUF, sbBl = sb + 2 * ABUF;
    const int tid = threadIdx.x;
    const int wid = tid >> 5, lane = tid & 31;
    const int warp_m = wid >> 2, warp_n = wid & 3;
    const int ltile = blockIdx.x, otile = blockIdx.y, n = blockIdx.z;

    const __half* Hh = in_hi + (size_t)n * HLC;
    const __half* Hl = in_lo + (size_t)n * HLC;

    float acc[4][4][4];
#pragma unroll
    for (int mi = 0; mi < 4; mi++)
#pragma unroll
        for (int ni = 0; ni < 4; ni++)
#pragma unroll
            for (int e = 0; e < 4; e++) acc[mi][ni][e] = 0.f;

    const int aRow = warp_m * 64 + (lane & 15);
    const int aCol = (lane >> 4) << 3;
    const int bRow = warp_n * 32 + ((lane & 7) | ((lane >> 4) << 3));
    const int bCol = ((lane >> 3) & 1) << 3;

#pragma unroll 1
    for (int t = 0; t < 3; t++) {
        const int shift = (t - 1) * d;
#pragma unroll 1
        for (int i0 = 0; i0 < HID; i0 += 64) {
            __syncthreads();                   // prior phase's ldsm done
            // A: weight slice [128 o][64 i]
            for (int idx = tid; idx < 1024; idx += 256) {
                const int r = idx >> 3, ch = idx & 7;
                const size_t gsrc = (size_t)t * WPLANE
                                  + (size_t)(otile * 128 + r) * HID + i0 + ch * 8;
                const uint32_t sdst = (uint32_t)(r * LDA + ch * 8) * 2;
                cp16(sbA + sdst, w16 + gsrc, 16);
            }
            // B: shifted activation slice [128 l][64 i] hi/lo, zero-padded
            for (int idx = tid; idx < 1024; idx += 256) {
                const int r = idx >> 3, ch = idx & 7;
                const int lsrc = ltile * 128 + r + shift;
                const bool ok = (lsrc >= 0) && (lsrc < CHLEN);
                const size_t goff = (size_t)(ok ? lsrc : 0) * HID + i0 + ch * 8;
                const int ssz = ok ? 16 : 0;
                const uint32_t sdst = (uint32_t)(r * LDA + ch * 8) * 2;
                cp16(sbBh + sdst, Hh + goff, ssz);
                cp16(sbBl + sdst, Hl + goff, ssz);
            }
            cp_commit_wait();
            __syncthreads();
#pragma unroll
            for (int ks = 0; ks < 4; ks++) {
                uint32_t a4[4][4], bh[8], bl[8];
#pragma unroll
                for (int mi = 0; mi < 4; mi++) {
                    const uint32_t off = (uint32_t)(((aRow + mi * 16) * LDA) + aCol + ks * 16) * 2;
                    ldsm_x4(a4[mi], sbA + off);
                }
#pragma unroll
                for (int bi = 0; bi < 2; bi++) {
                    const uint32_t off = (uint32_t)(((bRow + bi * 16) * LDA) + bCol + ks * 16) * 2;
                    ldsm_x4(&bh[bi * 4], sbBh + off);
                    ldsm_x4(&bl[bi * 4], sbBl + off);
                }
#pragma unroll
                for (int mi = 0; mi < 4; mi++)
#pragma unroll
                    for (int ni = 0; ni < 4; ni++)
                        mma_16816(acc[mi][ni], a4[mi], &bh[ni * 2]);   // W * Hhi
#pragma unroll
                for (int mi = 0; mi < 4; mi++)
#pragma unroll
                    for (int ni = 0; ni < 4; ni++)
                        mma_16816(acc[mi][ni], a4[mi], &bl[ni * 2]);   // W * Hlo
            }
        }
    }

    // ---- epilogue: bias + exact gelu + residual, stage [l][o], split store
    __syncthreads();
    __half* stage_hi = (__half*)smem;            // [128 l][136 o]
    __half* stage_lo = (__half*)(smem + 36864);
    const int g = lane >> 2, tg = lane & 3;
#pragma unroll
    for (int mi = 0; mi < 4; mi++) {
        const int row0 = warp_m * 64 + mi * 16 + g;
        const float b0 = bias[otile * 128 + row0];
        const float b8 = bias[otile * 128 + row0 + 8];
#pragma unroll
        for (int ni = 0; ni < 4; ni++) {
            const int col = warp_n * 32 + ni * 8 + tg * 2;
#pragma unroll
            for (int e = 0; e < 4; e++) {
                const int row = row0 + ((e >> 1) << 3);
                const int c   = col + (e & 1);
                float v = acc[mi][ni][e] + ((e < 2) ? b0 : b8);
                float r = fmaf(v, normcdff(v), v);             // gelu(v) + v
                __half h, l;
                split_f16(r, h, l);
                stage_hi[c * 136 + row] = h;
                stage_lo[c * 136 + row] = l;
            }
        }
    }
    __syncthreads();
    {
        const int row  = tid >> 1;                              // l-local
        const int half = tid & 1;                               // o 64-half
        const char* sh = (const char*)stage_hi + row * 272 + half * 128;
        const char* sl = (const char*)stage_lo + row * 272 + half * 128;
        __half* oh = out_hi + (size_t)n * HLC +
                     (size_t)(ltile * 128 + row) * HID + otile * 128 + half * 64;
        __half* ol = out_lo + (size_t)n * HLC +
                     (size_t)(ltile * 128 + row) * HID + otile * 128 + half * 64;
#pragma unroll
        for (int k = 0; k < 8; k++) {
            ((uint4*)oh)[k] = ((const uint4*)sh)[k];
            ((uint4*)ol)[k] = ((const uint4*)sl)[k];
        }
    }
}

// ---------------------------------------------------------------------------
// Profile head, [l][c] layout: out[l] = b + sum_k sum_c w[c][k] h[l+k-9][c]
// ---------------------------------------------------------------------------
#define PROF_Q_ROWS 531
#define PROF_SMEM   (PROF_Q_ROWS * 20 * 4 + 16 + HID * 20 * 4)

__global__ __launch_bounds__(256) void profile_head_kernel(
    const __half* __restrict__ in_hi, const __half* __restrict__ in_lo,
    const float* __restrict__ wprof, const float* __restrict__ bprof,
    float* __restrict__ out)
{
    extern __shared__ char smem[];
    float* Qs  = (float*)smem;                         // [531][20]
    float* wsh = (float*)(smem + PROF_Q_ROWS * 20 * 4 + 16);
    const int n = blockIdx.x, tid = threadIdx.x;
    const int wid = tid >> 5, lane = tid & 31;

    for (int i = tid; i < HID * 20; i += 256) wsh[i] = wprof[i];
    for (int i = tid; i < PROF_Q_ROWS * 20; i += 256) Qs[i] = 0.f;
    __syncthreads();

    const __half* Hh = in_hi + (size_t)n * HLC;
    const __half* Hl = in_lo + (size_t)n * HLC;
    for (int row = wid; row < CHLEN; row += 8) {
        uint4 uh = *(const uint4*)(Hh + (size_t)row * HID + lane * 8);
        uint4 ul = *(const uint4*)(Hl + (size_t)row * HID + lane * 8);
        const __half* ph = (const __half*)&uh;
        const __half* pl = (const __half*)&ul;
        float acc[20];
#pragma unroll
        for (int k = 0; k < 20; k++) acc[k] = 0.f;
#pragma unroll
        for (int cc = 0; cc < 8; cc++) {
            float hv = __half2float(ph[cc]) + __half2float(pl[cc]);
            const float* wr = &wsh[(lane * 8 + cc) * 20];
#pragma unroll
            for (int k = 0; k < 20; k++) acc[k] = fmaf(hv, wr[k], acc[k]);
        }
#pragma unroll
        for (int off = 16; off > 0; off >>= 1)
#pragma unroll
            for (int k = 0; k < 20; k++)
                acc[k] += __shfl_xor_sync(0xFFFFFFFF, acc[k], off);
        if (lane < 20) Qs[(row + 9) * 20 + lane] = acc[lane];
    }
    __syncthreads();

    const float bz = bprof[0];
    for (int l = tid; l < CHLEN; l += 256) {
        float s = bz;
#pragma unroll
        for (int k = 0; k < 20; k++) s += Qs[(l + k) * 20 + k];
        out[NCHUNK + (size_t)n * CHLEN + l] = s;
    }
}

// ---------------------------------------------------------------------------
// atpm head, [l][c] layout; n_peaks is int32 (JAX x64-disabled)
// ---------------------------------------------------------------------------
__global__ __launch_bounds__(256) void atpm_head_kernel(
    const __half* __restrict__ in_hi, const __half* __restrict__ in_lo,
    const float* __restrict__ watpm, const float* __restrict__ batpm,
    const int* __restrict__ npeaks, float* __restrict__ out)
{
    __shared__ float red[256];
    const int n = blockIdx.x, tid = threadIdx.x;
    const __half* Hh = in_hi + (size_t)n * HLC + tid;
    const __half* Hl = in_lo + (size_t)n * HLC + tid;
    float s = 0.f;
    for (int l = 0; l < CHLEN; l++)
        s += __half2float(Hh[(size_t)l * HID]) + __half2float(Hl[(size_t)l * HID]);
    red[tid] = s * watpm[tid];
    __syncthreads();
    for (int off = 128; off > 0; off >>= 1) {
        if (tid < off) red[tid] += red[tid + off];
        __syncthreads();
    }
    if (tid == 0) {
        float v = red[0] * (1.f / (float)CHLEN) + batpm[0];
        int b = n >> 7, p = n & 127;
        out[n] = (p < npeaks[b]) ? v : 0.f;
    }
}

// ---------------------------------------------------------------------------
extern "C" void kernel_launch(void* const* d_in, const int* in_sizes, int n_in,
                              void* d_out, int out_size)
{
    const float* x       = (const float*)d_in[0];
    const float* w_proj  = (const float*)d_in[1];
    const float* tower_w = (const float*)d_in[2];
    const float* tower_b = (const float*)d_in[3];
    const float* w_prof  = (const float*)d_in[4];
    const float* b_prof  = (const float*)d_in[5];
    const float* w_atpm  = (const float*)d_in[6];
    const float* b_atpm  = (const float*)d_in[7];
    const int*   n_peaks = (const int*)d_in[8];
    float* out = (float*)d_out;

    __half *hiA, *loA, *hiB, *loB, *w16, *xHi, *xLo, *wp16;
    cudaGetSymbolAddress((void**)&hiA, g_hiA);
    cudaGetSymbolAddress((void**)&loA, g_loA);
    cudaGetSymbolAddress((void**)&hiB, g_hiB);
    cudaGetSymbolAddress((void**)&loB, g_loB);
    cudaGetSymbolAddress((void**)&w16, g_w16);
    cudaGetSymbolAddress((void**)&xHi, g_xHi);
    cudaGetSymbolAddress((void**)&xLo, g_xLo);
    cudaGetSymbolAddress((void**)&wp16, g_wp16);

    cudaFuncSetAttribute(conv_mma_kernel,
                         cudaFuncAttributeMaxDynamicSharedMemorySize, SM_MMA);
    cudaFuncSetAttribute(proj_mma_kernel,
                         cudaFuncAttributeMaxDynamicSharedMemorySize, SM_MMA);
    cudaFuncSetAttribute(profile_head_kernel,
                         cudaFuncAttributeMaxDynamicSharedMemorySize, PROF_SMEM);

    wprep_kernel<<<DEPTH * 3 * WPLANE / 256, 256>>>(tower_w, w16);
    wpsplit_kernel<<<HID, 256>>>(w_proj, wp16);
    xsplit_kernel<<<NROWS, 256>>>(x, xHi, xLo);
    proj_mma_kernel<<<dim3(NROWS / 128, 2), 256, SM_MMA>>>(xHi, xLo, wp16, hiA, loA);

    __half *ch = hiA, *cl = loA, *nh = hiB, *nl = loB;
    for (int i = 0; i < DEPTH; i++) {
        int d = 2 << i;          // 2^(i+1)
        conv_mma_kernel<<<dim3(4, 2, NCHUNK), 256, SM_MMA>>>(
            ch, cl, w16 + (size_t)i * 3 * WPLANE,
            tower_b + i * HID, nh, nl, d);
        __half* t;
        t = ch; ch = nh; nh = t;
        t = cl; cl = nl; nl = t;
    }

    profile_head_kernel<<<NCHUNK, 256, PROF_SMEM>>>(ch, cl, w_prof, b_prof, out);
    atpm_head_kernel<<<NCHUNK, 256>>>(ch, cl, w_atpm, b_atpm, n_peaks, out);
}